// round 15
// baseline (speedup 1.0000x reference)
#include <cuda_runtime.h>
#include <cuda_bf16.h>
#include <cstdint>

typedef unsigned long long ull;

#define TILE_M   128
#define NTHREADS 512
#define MARGIN   6e-3f      // > 2*max|s_hat - s| = 3.2e-3 (single bf16 GEMM; R13-validated)
#define QCAP     2048

// ---------------- smem layout (bytes) ----------------
#define XT_OFF    0          // fp32 x  [128 r][65]   33280
#define A_OFF     33280      // bf16 x_hi [128][144]  18432  -> ends 51712
#define B_OFF     51712      // bf16 e_hi [512][144]  73728  -> ends 125440
#define QS_OFF    51712      // fp32 q  [128][65] ALIASES dead B after GEMM (33280)
#define T2_OFF    125440     // 512*4  -> 127488
#define T1_OFF    127488     // 128*4  -> 128000
#define KEY_OFF   128000     // ull[128] -> 129024
#define IND_OFF   129024     // int[128] -> 129536
#define QN_OFF    129536     // int (+pad 16) -> 129552
#define LRED_OFF  129552     // double[16] -> 129680
#define QBUF_OFF  129680     // int[QCAP] = 8192 -> 137872
#define SMEM_BYTES 137872

__device__ double   g_loss_sum = 0.0;
__device__ unsigned g_ticket   = 0;
__device__ float    g_t2[512];
__device__ uint32_t g_ehi[512 * 32];     // bf16x2 packed e_hi

__device__ __forceinline__ uint32_t smem_u32(const void* p) {
    uint32_t a;
    asm("{ .reg .u64 t; cvta.to.shared.u64 t, %1; cvt.u32.u64 %0, t; }" : "=r"(a) : "l"(p));
    return a;
}
__device__ __forceinline__ void ldsm4(uint32_t* r, uint32_t addr) {
    asm volatile("ldmatrix.sync.aligned.m8n8.x4.shared.b16 {%0,%1,%2,%3}, [%4];"
        : "=r"(r[0]), "=r"(r[1]), "=r"(r[2]), "=r"(r[3]) : "r"(addr));
}
__device__ __forceinline__ void mma_bf16(float* c, const uint32_t* a, uint32_t b0, uint32_t b1) {
    asm volatile("mma.sync.aligned.m16n8k16.row.col.f32.bf16.bf16.f32 "
        "{%0,%1,%2,%3}, {%4,%5,%6,%7}, {%8,%9}, {%0,%1,%2,%3};"
        : "+f"(c[0]), "+f"(c[1]), "+f"(c[2]), "+f"(c[3])
        : "r"(a[0]), "r"(a[1]), "r"(a[2]), "r"(a[3]), "r"(b0), "r"(b1));
}
__device__ __forceinline__ uint32_t bfp(float a, float b) {
    __nv_bfloat162 t = __floats2bfloat162_rn(a, b);
    return *(uint32_t*)&t;
}

// Exact chain (byte-identical to proven rel_err=0.0 kernels): sequential fmaf over
// d ascending, dist = fl( fl(t1 + t2) - 2*m ), packed-key min => first-index ties.
__device__ __forceinline__ void exact_gmem(int r, int k, const float* __restrict__ emb,
                                           const float* xt, const float* t1_s,
                                           const float* t2_s, ull* key_s) {
    const float4* p4 = (const float4*)(emb + (size_t)k * 64);
    const float* xr = xt + r * 65;
    float m = 0.0f;
    #pragma unroll 1
    for (int t = 0; t < 16; ++t) {
        float4 v = __ldg(p4 + t);
        m = fmaf(xr[4*t+0], v.x, m); m = fmaf(xr[4*t+1], v.y, m);
        m = fmaf(xr[4*t+2], v.z, m); m = fmaf(xr[4*t+3], v.w, m);
    }
    float dist = __fsub_rn(__fadd_rn(t1_s[r], t2_s[k]), 2.0f * m);
    atomicMin(key_s + r, ((ull)__float_as_uint(dist) << 32) | (unsigned)k);
}

// ---------------- prelude (per replay): exact t2 + bf16 e_hi ----------------
__global__ void vq_pre_kernel(const float* __restrict__ emb)
{
    int tid = threadIdx.x;
    if (tid < 512) {
        const float4* p4 = (const float4*)(emb + (size_t)tid * 64);
        float acc = 0.0f;
        #pragma unroll 1
        for (int t = 0; t < 16; ++t) {
            float4 v = __ldg(p4 + t);
            acc = __fadd_rn(acc, __fmul_rn(v.x, v.x));
            acc = __fadd_rn(acc, __fmul_rn(v.y, v.y));
            acc = __fadd_rn(acc, __fmul_rn(v.z, v.z));
            acc = __fadd_rn(acc, __fmul_rn(v.w, v.w));
        }
        g_t2[tid] = acc;
    }
    for (int i = tid; i < 512 * 32; i += blockDim.x) {
        float2 v = __ldg((const float2*)emb + i);
        g_ehi[i] = bfp(v.x, v.y);
    }
}

__global__ __launch_bounds__(NTHREADS, 1)
void vq_main_kernel(const float* __restrict__ lat,
                    const float* __restrict__ emb,
                    float* __restrict__ out,
                    long long numel, long long loss_idx, int grid_n)
{
    extern __shared__ unsigned char smem[];
    const uint32_t smem_base = smem_u32(smem);
    float*  xt    = (float*)(smem + XT_OFF);    // [r][65]
    float*  q_s   = (float*)(smem + QS_OFF);    // [r][65] aliases dead B after GEMM
    float*  t2_s  = (float*)(smem + T2_OFF);
    float*  t1_s  = (float*)(smem + T1_OFF);
    ull*    key_s = (ull*)(smem + KEY_OFF);
    int*    ind_s = (int*)(smem + IND_OFF);
    int*    qn_s  = (int*)(smem + QN_OFF);
    double* lred  = (double*)(smem + LRED_OFF);
    int*    qbuf  = (int*)(smem + QBUF_OFF);

    const int tid  = threadIdx.x;
    const int wid  = tid >> 5;
    const int lane = tid & 31;
    const int n0   = blockIdx.x * TILE_M;
    const int b    = n0 >> 12;
    const int p0   = n0 & 4095;
    const float* xg = lat + ((size_t)b << 18) + p0;

    if (tid == 0) *qn_s = 0;
    if (tid < 128) key_s[tid] = ~0ull;

    // ---- x: fp32 transposed [r][65] + bf16 hi tile (pitch 144) ----
    for (int i = tid; i < 64 * 128; i += NTHREADS) {
        int d = i >> 7, r = i & 127;
        float v = __ldg(&xg[(d << 12) + r]);
        xt[r * 65 + d] = v;
        *(__nv_bfloat16*)(smem + A_OFF + r * 144 + d * 2) = __float2bfloat16(v);
    }
    // ---- B: e_hi bf16 (pitch 144) + t2 from precomputed globals ----
    for (int i = tid; i < 512 * 32; i += NTHREADS) {
        int k = i >> 5, d2 = i & 31;
        *(uint32_t*)(smem + B_OFF + k * 144 + d2 * 4) = __ldg(&g_ehi[i]);
    }
    if (tid < 512) t2_s[tid] = g_t2[tid];
    __syncthreads();

    // ---- t1[r]: sequential fp32 chain over d (EXACT) ----
    if (tid < 128) {
        const float* xr = xt + tid * 65;
        float acc = 0.0f;
        #pragma unroll 1
        for (int d = 0; d < 64; ++d)
            acc = __fadd_rn(acc, __fmul_rn(xr[d], xr[d]));
        t1_s[tid] = acc;
    }

    // ---- single-pass GEMM + running-min candidate queueing ----
    const int g = lane >> 2, tq = lane & 3;
    const int lrow = lane & 15, lsel = lane >> 4;
    const int R0 = (wid >> 1) * 16;       // 8 row groups of 16
    const int C0 = (wid & 1) * 256;       // 2 col groups of 256
    const int rlo = R0 + g, rhi = R0 + 8 + g;

    uint32_t aH[4][4];
    #pragma unroll
    for (int ks = 0; ks < 4; ++ks)
        ldsm4(aH[ks], smem_base + A_OFF + (R0 + lrow) * 144 + ks * 32 + lsel * 16);

    float run0 = 3.4e38f, run1 = 3.4e38f;   // running min across chunks (superset-safe)

    #pragma unroll 1
    for (int ch = 0; ch < 4; ++ch) {
        float acc[8][4];
        #pragma unroll
        for (int nj = 0; nj < 8; ++nj)
            #pragma unroll
            for (int q = 0; q < 4; ++q) acc[nj][q] = 0.0f;

        #pragma unroll
        for (int ks = 0; ks < 4; ++ks) {
            uint32_t bF[4][4];
            #pragma unroll
            for (int nb = 0; nb < 4; ++nb)
                ldsm4(bF[nb], smem_base + B_OFF +
                      (C0 + ch * 64 + nb * 16 + lrow) * 144 + ks * 32 + lsel * 16);
            #pragma unroll
            for (int nb = 0; nb < 4; ++nb) {
                mma_bf16(acc[2*nb],   aH[ks], bF[nb][0], bF[nb][2]);
                mma_bf16(acc[2*nb+1], aH[ks], bF[nb][1], bF[nb][3]);
            }
        }

        // s_hat = t2[k] - 2*m_hat ; per-(row,chunk) min via quad shuffles
        float mn0 = 3.4e38f, mn1 = 3.4e38f;
        #pragma unroll
        for (int nj = 0; nj < 8; ++nj) {
            int k0 = C0 + ch * 64 + nj * 8 + 2 * tq;
            float2 t2v = *(const float2*)(t2_s + k0);
            acc[nj][0] = t2v.x - 2.0f * acc[nj][0];
            acc[nj][1] = t2v.y - 2.0f * acc[nj][1];
            acc[nj][2] = t2v.x - 2.0f * acc[nj][2];
            acc[nj][3] = t2v.y - 2.0f * acc[nj][3];
            mn0 = fminf(mn0, fminf(acc[nj][0], acc[nj][1]));
            mn1 = fminf(mn1, fminf(acc[nj][2], acc[nj][3]));
        }
        mn0 = fminf(mn0, __shfl_xor_sync(0xffffffffu, mn0, 1));
        mn0 = fminf(mn0, __shfl_xor_sync(0xffffffffu, mn0, 2));
        mn1 = fminf(mn1, __shfl_xor_sync(0xffffffffu, mn1, 1));
        mn1 = fminf(mn1, __shfl_xor_sync(0xffffffffu, mn1, 2));
        run0 = fminf(run0, mn0);
        run1 = fminf(run1, mn1);
        const float thr0 = run0 + MARGIN, thr1 = run1 + MARGIN;

        // queue candidates: {s_hat < runmin + margin} is a superset of the
        // required set (runmin >= global rowmin; margin > 2*|s_hat - s|max)
        #pragma unroll
        for (int nj = 0; nj < 8; ++nj) {
            int k0 = C0 + ch * 64 + nj * 8 + 2 * tq;
            #pragma unroll
            for (int q = 0; q < 4; ++q) {
                float s  = acc[nj][q];
                int   r  = (q < 2) ? rlo : rhi;
                float th = (q < 2) ? thr0 : thr1;
                int   k  = k0 + (q & 1);
                if (s < th) {
                    int slot = atomicAdd(qn_s, 1);
                    if (slot < QCAP) qbuf[slot] = (r << 16) | k;
                    else exact_gmem(r, k, emb, xt, t1_s, t2_s, key_s);
                }
            }
        }
    }
    __syncthreads();

    // ---- cooperative exact recheck of queued candidates ----
    {
        int nq = *qn_s; if (nq > QCAP) nq = QCAP;
        for (int q = tid; q < nq; q += NTHREADS) {
            int ent = qbuf[q];
            exact_gmem(ent >> 16, ent & 0xffff, emb, xt, t1_s, t2_s, key_s);
        }
    }
    __syncthreads();
    if (tid < 128) ind_s[tid] = (int)(key_s[tid] & 0xffffffffu);
    __syncthreads();

    // ---- coalesced row-wise gather of selected codes into q_s[128][65] ----
    // float4 LDG (coalesced, L2-hot); scalar STS.32 — pitch-65 rows are only
    // 4B-aligned, so a vector STS would fault (R14 bug).
    for (int i = tid; i < 128 * 16; i += NTHREADS) {
        int rr = i >> 4, t = i & 15;
        float4 v = __ldg((const float4*)(emb + (size_t)ind_s[rr] * 64) + t);
        float* qp = q_s + rr * 65 + 4 * t;
        qp[0] = v.x; qp[1] = v.y; qp[2] = v.z; qp[3] = v.w;
    }
    __syncthreads();

    // ---- straight-through output + loss (proven path) ----
    // q_s read: addr = rr*65 + d, consecutive lanes -> consecutive rr,
    // stride 65 == 1 (mod 32) -> conflict-free; STG fully coalesced.
    float lsum = 0.0f;
    const size_t obase = ((size_t)b << 18) + p0;
    for (int i = tid; i < 64 * 128; i += NTHREADS) {
        int d = i >> 7, rr = i & 127;
        float e = q_s[rr * 65 + d];
        float x = xt[rr * 65 + d];
        float qm = __fsub_rn(e, x);                             // fl(q - lat)
        out[obase + ((size_t)d << 12) + rr] = __fadd_rn(x, qm); // fl(lat + fl(q-lat))
        lsum = fmaf(qm, qm, lsum);
    }
    #pragma unroll
    for (int off = 16; off > 0; off >>= 1)
        lsum += __shfl_xor_sync(0xffffffffu, lsum, off);
    if (lane == 0) lred[wid] = (double)lsum;
    __syncthreads();

    if (tid == 0) {
        double s = 0.0;
        #pragma unroll
        for (int w = 0; w < NTHREADS / 32; ++w) s += lred[w];
        atomicAdd(&g_loss_sum, s);
        __threadfence();
        unsigned ticket = atomicAdd(&g_ticket, 1u);
        if (ticket == (unsigned)(grid_n - 1)) {
            double tot = atomicAdd(&g_loss_sum, 0.0);
            float lm = (float)(tot / (double)numel);
            out[loss_idx] = __fadd_rn(__fmul_rn(lm, 0.25f), lm);
            g_loss_sum = 0.0;
            g_ticket   = 0;
            __threadfence();
        }
    }
}

extern "C" void kernel_launch(void* const* d_in, const int* in_sizes, int n_in,
                              void* d_out, int out_size)
{
    const float* lat = (const float*)d_in[0];
    const float* emb = (const float*)d_in[1];
    float* out = (float*)d_out;

    const long long numel = (long long)in_sizes[0];     // 8388608
    const int n_rows = (int)(numel / 64);               // 131072
    const int grid   = n_rows / TILE_M;                 // 1024

    cudaFuncSetAttribute(vq_main_kernel,
                         cudaFuncAttributeMaxDynamicSharedMemorySize, SMEM_BYTES);

    long long loss_idx = (out_size > numel) ? numel : (long long)out_size - 1;
    vq_pre_kernel<<<1, 512>>>(emb);
    vq_main_kernel<<<grid, NTHREADS, SMEM_BYTES>>>(lat, emb, out,
                                                   numel, loss_idx, grid);
}

// round 16
// speedup vs baseline: 1.0865x; 1.0865x over previous
#include <cuda_runtime.h>
#include <cuda_bf16.h>
#include <cstdint>

typedef unsigned long long ull;

#define TILE_M   128
#define NTHREADS 512
#define MARGIN   6e-3f      // > 2*max|s_hat - s| = 3.2e-3 (single bf16 GEMM; validated R13/R15)
#define QCAP     6144

// ---------------- smem layout (bytes) — identical to the 233.5us R11 kernel ----------------
#define XT_OFF    0          // fp32 x  [128 r][65]   33280
#define A_OFF     33280      // bf16 x_hi [128][144]  18432
#define B_OFF     70144      // bf16 e_hi [512][144]  73728 (ends 143872)
#define E32_OFF   33280      // fp32 emb [512][65] ALIASES A/B post-GEMM (133120, ends 166400)
#define T2_OFF    166400     // 512*4
#define T1_OFF    168448     // 128*4
#define KEY_OFF   168960     // ull[128]
#define IND_OFF   169984     // int[128]
#define QN_OFF    170496     // int (+pad)
#define LRED_OFF  170512     // double[16]
#define QBUF_OFF  170640     // int[QCAP] = 24576
#define SMEM_BYTES 195232

__device__ double   g_loss_sum = 0.0;
__device__ unsigned g_ticket   = 0;
__device__ float    g_t2[512];
__device__ uint32_t g_ehi[512 * 32];     // bf16x2 packed e_hi

__device__ __forceinline__ uint32_t smem_u32(const void* p) {
    uint32_t a;
    asm("{ .reg .u64 t; cvta.to.shared.u64 t, %1; cvt.u32.u64 %0, t; }" : "=r"(a) : "l"(p));
    return a;
}
__device__ __forceinline__ void ldsm4(uint32_t* r, uint32_t addr) {
    asm volatile("ldmatrix.sync.aligned.m8n8.x4.shared.b16 {%0,%1,%2,%3}, [%4];"
        : "=r"(r[0]), "=r"(r[1]), "=r"(r[2]), "=r"(r[3]) : "r"(addr));
}
__device__ __forceinline__ void mma_bf16(float* c, const uint32_t* a, uint32_t b0, uint32_t b1) {
    asm volatile("mma.sync.aligned.m16n8k16.row.col.f32.bf16.bf16.f32 "
        "{%0,%1,%2,%3}, {%4,%5,%6,%7}, {%8,%9}, {%0,%1,%2,%3};"
        : "+f"(c[0]), "+f"(c[1]), "+f"(c[2]), "+f"(c[3])
        : "r"(a[0]), "r"(a[1]), "r"(a[2]), "r"(a[3]), "r"(b0), "r"(b1));
}
__device__ __forceinline__ uint32_t bfp(float a, float b) {
    __nv_bfloat162 t = __floats2bfloat162_rn(a, b);
    return *(uint32_t*)&t;
}

// Exact chain (byte-identical to proven rel_err=0.0 kernels): sequential fmaf over
// d ascending, dist = fl( fl(t1 + t2) - 2*m ), packed-key min => first-index ties.
__device__ __forceinline__ void exact_smem(int r, int k, const float* xt, const float* e32,
                                           const float* t1_s, const float* t2_s, ull* key_s) {
    const float* xr = xt  + r * 65;
    const float* er = e32 + k * 65;
    float m = 0.0f;
    #pragma unroll 1
    for (int d = 0; d < 64; ++d) m = fmaf(xr[d], er[d], m);
    float dist = __fsub_rn(__fadd_rn(t1_s[r], t2_s[k]), 2.0f * m);
    atomicMin(key_s + r, ((ull)__float_as_uint(dist) << 32) | (unsigned)k);
}
__device__ __forceinline__ void exact_gmem(int r, int k, const float* __restrict__ emb,
                                           const float* xt, const float* t1_s,
                                           const float* t2_s, ull* key_s) {
    const float4* p4 = (const float4*)(emb + (size_t)k * 64);
    const float* xr = xt + r * 65;
    float m = 0.0f;
    #pragma unroll 1
    for (int t = 0; t < 16; ++t) {
        float4 v = __ldg(p4 + t);
        m = fmaf(xr[4*t+0], v.x, m); m = fmaf(xr[4*t+1], v.y, m);
        m = fmaf(xr[4*t+2], v.z, m); m = fmaf(xr[4*t+3], v.w, m);
    }
    float dist = __fsub_rn(__fadd_rn(t1_s[r], t2_s[k]), 2.0f * m);
    atomicMin(key_s + r, ((ull)__float_as_uint(dist) << 32) | (unsigned)k);
}

// ---------------- prelude (per replay): exact t2 + bf16 e_hi ----------------
__global__ void vq_pre_kernel(const float* __restrict__ emb)
{
    int tid = threadIdx.x;
    if (tid < 512) {
        const float4* p4 = (const float4*)(emb + (size_t)tid * 64);
        float acc = 0.0f;
        #pragma unroll 1
        for (int t = 0; t < 16; ++t) {
            float4 v = __ldg(p4 + t);
            acc = __fadd_rn(acc, __fmul_rn(v.x, v.x));
            acc = __fadd_rn(acc, __fmul_rn(v.y, v.y));
            acc = __fadd_rn(acc, __fmul_rn(v.z, v.z));
            acc = __fadd_rn(acc, __fmul_rn(v.w, v.w));
        }
        g_t2[tid] = acc;
    }
    for (int i = tid; i < 512 * 32; i += blockDim.x) {
        float2 v = __ldg((const float2*)emb + i);
        g_ehi[i] = bfp(v.x, v.y);
    }
}

__global__ __launch_bounds__(NTHREADS, 1)
void vq_main_kernel(const float* __restrict__ lat,
                    const float* __restrict__ emb,
                    float* __restrict__ out,
                    long long numel, long long loss_idx, int grid_n)
{
    extern __shared__ unsigned char smem[];
    const uint32_t smem_base = smem_u32(smem);
    float*  xt    = (float*)(smem + XT_OFF);    // [r][65]
    float*  e32   = (float*)(smem + E32_OFF);   // [k][65] after GEMM
    float*  t1_s  = (float*)(smem + T1_OFF);
    float*  t2_s  = (float*)(smem + T2_OFF);
    ull*    key_s = (ull*)(smem + KEY_OFF);
    int*    ind_s = (int*)(smem + IND_OFF);
    int*    qn_s  = (int*)(smem + QN_OFF);
    double* lred  = (double*)(smem + LRED_OFF);
    int*    qbuf  = (int*)(smem + QBUF_OFF);

    const int tid  = threadIdx.x;
    const int wid  = tid >> 5;
    const int lane = tid & 31;
    const int n0   = blockIdx.x * TILE_M;
    const int b    = n0 >> 12;
    const int p0   = n0 & 4095;
    const float* xg = lat + ((size_t)b << 18) + p0;

    if (tid == 0) *qn_s = 0;
    if (tid < 128) key_s[tid] = ~0ull;
    if (tid < 512) t2_s[tid] = g_t2[tid];

    // ---- x: fp32 transposed [r][65] + bf16 hi tile (pitch 144) ----
    for (int i = tid; i < 64 * 128; i += NTHREADS) {
        int d = i >> 7, r = i & 127;
        float v = __ldg(&xg[(d << 12) + r]);
        xt[r * 65 + d] = v;
        *(__nv_bfloat16*)(smem + A_OFF + r * 144 + d * 2) = __float2bfloat16(v);
    }
    // ---- B: e_hi bf16 (pitch 144) from precomputed global ----
    for (int i = tid; i < 512 * 32; i += NTHREADS) {
        int k = i >> 5, d2 = i & 31;
        *(uint32_t*)(smem + B_OFF + k * 144 + d2 * 4) = __ldg(&g_ehi[i]);
    }
    __syncthreads();

    // ---- t1[r]: sequential fp32 chain over d (EXACT) ----
    if (tid < 128) {
        const float* xr = xt + tid * 65;
        float acc = 0.0f;
        #pragma unroll 1
        for (int d = 0; d < 64; ++d)
            acc = __fadd_rn(acc, __fmul_rn(xr[d], xr[d]));
        t1_s[tid] = acc;
    }

    // ---- single-pass GEMM + running-min candidate queueing ----
    const int g = lane >> 2, tq = lane & 3;
    const int lrow = lane & 15, lsel = lane >> 4;
    const int R0 = (wid >> 1) * 16;       // 8 row groups of 16
    const int C0 = (wid & 1) * 256;       // 2 col groups of 256
    const int rlo = R0 + g, rhi = R0 + 8 + g;

    uint32_t aH[4][4];
    #pragma unroll
    for (int ks = 0; ks < 4; ++ks)
        ldsm4(aH[ks], smem_base + A_OFF + (R0 + lrow) * 144 + ks * 32 + lsel * 16);

    float run0 = 3.4e38f, run1 = 3.4e38f;   // running min across chunks (superset-safe)

    #pragma unroll 1
    for (int ch = 0; ch < 4; ++ch) {
        float acc[8][4];
        #pragma unroll
        for (int nj = 0; nj < 8; ++nj)
            #pragma unroll
            for (int q = 0; q < 4; ++q) acc[nj][q] = 0.0f;

        #pragma unroll
        for (int ks = 0; ks < 4; ++ks) {
            uint32_t bF[4][4];
            #pragma unroll
            for (int nb = 0; nb < 4; ++nb)
                ldsm4(bF[nb], smem_base + B_OFF +
                      (C0 + ch * 64 + nb * 16 + lrow) * 144 + ks * 32 + lsel * 16);
            #pragma unroll
            for (int nb = 0; nb < 4; ++nb) {
                mma_bf16(acc[2*nb],   aH[ks], bF[nb][0], bF[nb][2]);
                mma_bf16(acc[2*nb+1], aH[ks], bF[nb][1], bF[nb][3]);
            }
        }

        // s_hat = t2[k] - 2*m_hat ; per-(row,chunk) min via quad shuffles
        float mn0 = 3.4e38f, mn1 = 3.4e38f;
        #pragma unroll
        for (int nj = 0; nj < 8; ++nj) {
            int k0 = C0 + ch * 64 + nj * 8 + 2 * tq;
            float2 t2v = *(const float2*)(t2_s + k0);
            acc[nj][0] = t2v.x - 2.0f * acc[nj][0];
            acc[nj][1] = t2v.y - 2.0f * acc[nj][1];
            acc[nj][2] = t2v.x - 2.0f * acc[nj][2];
            acc[nj][3] = t2v.y - 2.0f * acc[nj][3];
            mn0 = fminf(mn0, fminf(acc[nj][0], acc[nj][1]));
            mn1 = fminf(mn1, fminf(acc[nj][2], acc[nj][3]));
        }
        mn0 = fminf(mn0, __shfl_xor_sync(0xffffffffu, mn0, 1));
        mn0 = fminf(mn0, __shfl_xor_sync(0xffffffffu, mn0, 2));
        mn1 = fminf(mn1, __shfl_xor_sync(0xffffffffu, mn1, 1));
        mn1 = fminf(mn1, __shfl_xor_sync(0xffffffffu, mn1, 2));
        run0 = fminf(run0, mn0);
        run1 = fminf(run1, mn1);
        const float thr0 = run0 + MARGIN, thr1 = run1 + MARGIN;

        // queue candidates: {s_hat < runmin + margin} is a superset of the
        // required set (runmin >= global rowmin; margin > 2*|s_hat - s|max)
        #pragma unroll
        for (int nj = 0; nj < 8; ++nj) {
            int k0 = C0 + ch * 64 + nj * 8 + 2 * tq;
            #pragma unroll
            for (int q = 0; q < 4; ++q) {
                float s  = acc[nj][q];
                int   r  = (q < 2) ? rlo : rhi;
                float th = (q < 2) ? thr0 : thr1;
                int   k  = k0 + (q & 1);
                if (s < th) {
                    int slot = atomicAdd(qn_s, 1);
                    if (slot < QCAP) qbuf[slot] = (r << 16) | k;
                    else exact_gmem(r, k, emb, xt, t1_s, t2_s, key_s);
                }
            }
        }
    }
    __syncthreads();

    // ---- overwrite dead A/B region with fp32 codebook [k][65] ----
    // float4 LDG (coalesced, L2-hot) + 4 scalar STS (pitch-65 rows are 4B-aligned)
    for (int i = tid; i < 512 * 16; i += NTHREADS) {
        int k = i >> 4, t = i & 15;
        float4 v = __ldg((const float4*)emb + i);
        float* ep = e32 + k * 65 + 4 * t;
        ep[0] = v.x; ep[1] = v.y; ep[2] = v.z; ep[3] = v.w;
    }
    __syncthreads();

    // ---- cooperative exact recheck of queued candidates (smem-resident) ----
    {
        int nq = *qn_s; if (nq > QCAP) nq = QCAP;
        for (int q = tid; q < nq; q += NTHREADS) {
            int ent = qbuf[q];
            exact_smem(ent >> 16, ent & 0xffff, xt, e32, t1_s, t2_s, key_s);
        }
    }
    __syncthreads();
    if (tid < 128) ind_s[tid] = (int)(key_s[tid] & 0xffffffffu);
    __syncthreads();

    // ---- straight-through output + loss (proven path, e from smem fp32) ----
    float lsum = 0.0f;
    const size_t obase = ((size_t)b << 18) + p0;
    for (int i = tid; i < 64 * 128; i += NTHREADS) {
        int d = i >> 7, rr = i & 127;
        float e = e32[ind_s[rr] * 65 + d];
        float x = xt[rr * 65 + d];
        float qm = __fsub_rn(e, x);                             // fl(q - lat)
        out[obase + ((size_t)d << 12) + rr] = __fadd_rn(x, qm); // fl(lat + fl(q-lat))
        lsum = fmaf(qm, qm, lsum);
    }
    #pragma unroll
    for (int off = 16; off > 0; off >>= 1)
        lsum += __shfl_xor_sync(0xffffffffu, lsum, off);
    if (lane == 0) lred[wid] = (double)lsum;
    __syncthreads();

    if (tid == 0) {
        double s = 0.0;
        #pragma unroll
        for (int w = 0; w < NTHREADS / 32; ++w) s += lred[w];
        atomicAdd(&g_loss_sum, s);
        __threadfence();
        unsigned ticket = atomicAdd(&g_ticket, 1u);
        if (ticket == (unsigned)(grid_n - 1)) {
            double tot = atomicAdd(&g_loss_sum, 0.0);
            float lm = (float)(tot / (double)numel);
            out[loss_idx] = __fadd_rn(__fmul_rn(lm, 0.25f), lm);
            g_loss_sum = 0.0;
            g_ticket   = 0;
            __threadfence();
        }
    }
}

extern "C" void kernel_launch(void* const* d_in, const int* in_sizes, int n_in,
                              void* d_out, int out_size)
{
    const float* lat = (const float*)d_in[0];
    const float* emb = (const float*)d_in[1];
    float* out = (float*)d_out;

    const long long numel = (long long)in_sizes[0];     // 8388608
    const int n_rows = (int)(numel / 64);               // 131072
    const int grid   = n_rows / TILE_M;                 // 1024

    cudaFuncSetAttribute(vq_main_kernel,
                         cudaFuncAttributeMaxDynamicSharedMemorySize, SMEM_BYTES);

    long long loss_idx = (out_size > numel) ? numel : (long long)out_size - 1;
    vq_pre_kernel<<<1, 512>>>(emb);
    vq_main_kernel<<<grid, NTHREADS, SMEM_BYTES>>>(lat, emb, out,
                                                   numel, loss_idx, grid);
}